// round 5
// baseline (speedup 1.0000x reference)
#include <cuda_runtime.h>
#include <cuda_fp16.h>
#include <cuda_bf16.h>

// ---------------------------------------------------------------------------
// GAT (2-layer, H=4, D=32, IN=128) on GB300, round 5.
// ONE persistent mega-kernel: CSR build + 2x(fused GEMM + single-pass agg),
// separated by software grid barriers (sense-reversing, co-residency forced
// via __launch_bounds__). Kills ~9 kernel-launch overheads.
// ---------------------------------------------------------------------------

#define NN 50000
#define EE 800000
#define FDIM 128
#define NEG_SLOPE 0.2f
#define GRID 592          // 148 SMs x 4 blocks
#define TPB 256
#define NSEG 196          // ceil(50000/256)
#define GTM 64
#define GTK 32
#define NGEMM ((NN + GTM - 1) / GTM)
#define AGG_WARPS 8

typedef unsigned long long ull;

// -------------------- scratch (static device globals) ----------------------
__device__ __half g_feat_h[NN * FDIM];   // 12.8 MB fp16 features, head-interleaved
__device__ float  g_h1[NN * FDIM];       // 25.6 MB layer-1 output
__device__ int    g_csr_src[EE];
__device__ int    g_cnt[NN];
__device__ int    g_row[NN];
__device__ int    g_pos[NN];
__device__ float  g_el[NN * 4];
__device__ float  g_er[NN * 4];
__device__ int    g_bsum[NSEG];
__device__ int    g_bar_count;           // zero-init; returns to 0 each launch
__device__ int    g_bar_sense;           // zero-init; even #barriers -> returns to 0

// -------------------- shared memory union -----------------------------------
struct SMem {
    union {
        struct { float Xs[GTK][GTM + 2]; float Ws[GTK][FDIM]; } gi;   // 24832 B
        __half Hs[GTM][FDIM];                                          // 16384 B
        struct { float4 w[AGG_WARPS][33]; int s[AGG_WARPS][33]; } agg; // 5280 B
        struct { int warp[8]; int woff[8]; int arr[264]; } scan;       // 1120 B
    } u;
    int bsense;
};

// -------------------- f32x2 helpers -----------------------------------------
__device__ __forceinline__ ull pk2(float lo, float hi) {
    ull r; asm("mov.b64 %0, {%1, %2};" : "=l"(r) : "f"(lo), "f"(hi)); return r;
}
__device__ __forceinline__ void ffma2(ull& d, ull a, ull b) {
    asm("fma.rn.f32x2 %0, %1, %2, %0;" : "+l"(d) : "l"(a), "l"(b));
}
__device__ __forceinline__ float2 unpk(ull v) {
    float2 f; asm("mov.b64 {%0, %1}, %2;" : "=f"(f.x), "=f"(f.y) : "l"(v)); return f;
}

// -------------------- grid barrier ------------------------------------------
__device__ __forceinline__ void gbar(SMem* sm) {
    __syncthreads();
    if (threadIdx.x == 0) {
        int want = sm->bsense ^ 1;
        __threadfence();
        int a = atomicAdd(&g_bar_count, 1);
        if (a == (int)gridDim.x - 1) {
            atomicExch(&g_bar_count, 0);
            __threadfence();
            atomicExch(&g_bar_sense, want);
        } else {
            while (*(volatile int*)&g_bar_sense != want) __nanosleep(128);
        }
        __threadfence();
        sm->bsense = want;
    }
    __syncthreads();
}

// -------------------- math helpers ------------------------------------------
__device__ __forceinline__ float lrelu(float x) { return x > 0.f ? x : NEG_SLOPE * x; }
__device__ __forceinline__ float elu1(float x)  { return x > 0.f ? x : (__expf(x) - 1.f); }

// -------------------- GEMM phase (block-stride over tiles) ------------------
__device__ void gemm_phase(SMem* sm, const float* __restrict__ X,
                           const float* __restrict__ W,
                           const float* __restrict__ al,
                           const float* __restrict__ ar) {
    int t = threadIdx.x;
    int tx = t & 31, ty = t >> 5;

    for (int tile = blockIdx.x; tile < NGEMM; tile += gridDim.x) {
        int row0 = tile * GTM;
        ull acc[4][4];
#pragma unroll
        for (int p = 0; p < 4; p++)
#pragma unroll
            for (int c = 0; c < 4; c++) acc[p][c] = 0ull;

        for (int kc = 0; kc < FDIM; kc += GTK) {
#pragma unroll
            for (int i = 0; i < 8; i++) {
                int id = t + i * 256;
                int r = id >> 5, c = id & 31;
                int gr = row0 + r;
                sm->u.gi.Xs[c][r] = (gr < NN) ? X[gr * FDIM + kc + c] : 0.f;
            }
#pragma unroll
            for (int i = 0; i < 16; i++) {
                int id = t + i * 256;
                int r = id >> 7, c = id & 127;
                sm->u.gi.Ws[r][c] = W[(kc + r) * FDIM + c];
            }
            __syncthreads();
#pragma unroll
            for (int k = 0; k < GTK; k++) {
                float4 bv = *reinterpret_cast<const float4*>(&sm->u.gi.Ws[k][tx * 4]);
                ull b0 = pk2(bv.x, bv.x), b1 = pk2(bv.y, bv.y);
                ull b2 = pk2(bv.z, bv.z), b3 = pk2(bv.w, bv.w);
#pragma unroll
                for (int p = 0; p < 4; p++) {
                    ull a = *reinterpret_cast<const ull*>(&sm->u.gi.Xs[k][ty * 8 + p * 2]);
                    ffma2(acc[p][0], a, b0);
                    ffma2(acc[p][1], a, b1);
                    ffma2(acc[p][2], a, b2);
                    ffma2(acc[p][3], a, b3);
                }
            }
            __syncthreads();
        }

        // epilogue: fp16 emit (head-interleaved, Hs aliases Xs/Ws) + el/er
        float4 alv = *reinterpret_cast<const float4*>(&al[tx * 4]);
        float4 arv = *reinterpret_cast<const float4*>(&ar[tx * 4]);
        int head = tx >> 3;
#pragma unroll
        for (int p = 0; p < 4; p++) {
            float2 v0 = unpk(acc[p][0]);
            float2 v1 = unpk(acc[p][1]);
            float2 v2 = unpk(acc[p][2]);
            float2 v3 = unpk(acc[p][3]);
            int r0 = ty * 8 + p * 2, r1 = r0 + 1;
#pragma unroll
            for (int c = 0; c < 4; c++) {
                int col = tx * 4 + c;
                int pos = ((col & 31) << 2) | (col >> 5);
                float lo = (c == 0) ? v0.x : (c == 1) ? v1.x : (c == 2) ? v2.x : v3.x;
                float hi = (c == 0) ? v0.y : (c == 1) ? v1.y : (c == 2) ? v2.y : v3.y;
                sm->u.Hs[r0][pos] = __float2half(lo);
                sm->u.Hs[r1][pos] = __float2half(hi);
            }
            float pl0 = v0.x * alv.x + v1.x * alv.y + v2.x * alv.z + v3.x * alv.w;
            float pr0 = v0.x * arv.x + v1.x * arv.y + v2.x * arv.z + v3.x * arv.w;
            float pl1 = v0.y * alv.x + v1.y * alv.y + v2.y * alv.z + v3.y * alv.w;
            float pr1 = v0.y * arv.x + v1.y * arv.y + v2.y * arv.z + v3.y * arv.w;
#pragma unroll
            for (int off = 4; off; off >>= 1) {
                pl0 += __shfl_xor_sync(0xffffffffu, pl0, off);
                pr0 += __shfl_xor_sync(0xffffffffu, pr0, off);
                pl1 += __shfl_xor_sync(0xffffffffu, pl1, off);
                pr1 += __shfl_xor_sync(0xffffffffu, pr1, off);
            }
            if ((tx & 7) == 0) {
                if (row0 + r0 < NN) {
                    g_el[(row0 + r0) * 4 + head] = pl0;
                    g_er[(row0 + r0) * 4 + head] = pr0;
                }
                if (row0 + r1 < NN) {
                    g_el[(row0 + r1) * 4 + head] = pl1;
                    g_er[(row0 + r1) * 4 + head] = pr1;
                }
            }
        }
        __syncthreads();
#pragma unroll
        for (int i = t; i < GTM * 16; i += 256) {
            int r = i >> 4, c = i & 15;
            int gr = row0 + r;
            if (gr < NN)
                reinterpret_cast<uint4*>(g_feat_h + (size_t)gr * FDIM)[c] =
                    reinterpret_cast<const uint4*>(&sm->u.Hs[r][0])[c];
        }
        __syncthreads();   // protect smem reuse for next tile
    }
}

// -------------------- agg phase (warp-stride over nodes) --------------------
// MODE 1: layer1 -> elu, 128 feats to g_h1.  MODE 2: head-mean, 32 feats to out.
template <int MODE>
__device__ void agg_phase(SMem* sm, const float* __restrict__ resid,
                          const float* __restrict__ bias, float* __restrict__ out) {
    int wid  = threadIdx.x >> 5;
    int lane = threadIdx.x & 31;
    int gw   = blockIdx.x * AGG_WARPS + wid;
    int nw   = gridDim.x * AGG_WARPS;

    for (int node = gw; node < NN; node += nw) {
        int base = g_row[node];
        int deg  = g_cnt[node];
        float4 er4 = reinterpret_cast<const float4*>(g_er)[node];

        float sx = 0.f, sy = 0.f, sz = 0.f, sw = 0.f;
        float a0 = 0.f, a1 = 0.f, a2 = 0.f, a3 = 0.f;

        for (int c0 = 0; c0 < deg; c0 += 32) {
            int m = deg - c0; if (m > 32) m = 32;
            if (lane < m) {
                int s = g_csr_src[base + c0 + lane];
                float4 l4 = reinterpret_cast<const float4*>(g_el)[s];
                float4 w4;
                w4.x = __expf(lrelu(l4.x + er4.x));
                w4.y = __expf(lrelu(l4.y + er4.y));
                w4.z = __expf(lrelu(l4.z + er4.z));
                w4.w = __expf(lrelu(l4.w + er4.w));
                sx += w4.x; sy += w4.y; sz += w4.z; sw += w4.w;
                sm->u.agg.s[wid][lane] = s;
                sm->u.agg.w[wid][lane] = w4;
            }
            __syncwarp();
            int j = 0;
            for (; j + 3 < m; j += 4) {
                int   s0 = sm->u.agg.s[wid][j];
                int   s1 = sm->u.agg.s[wid][j + 1];
                int   s2 = sm->u.agg.s[wid][j + 2];
                int   s3 = sm->u.agg.s[wid][j + 3];
                float4 w0 = sm->u.agg.w[wid][j];
                float4 w1 = sm->u.agg.w[wid][j + 1];
                float4 w2 = sm->u.agg.w[wid][j + 2];
                float4 w3 = sm->u.agg.w[wid][j + 3];
                uint2 u0 = *reinterpret_cast<const uint2*>(g_feat_h + (size_t)s0 * FDIM + lane * 4);
                uint2 u1 = *reinterpret_cast<const uint2*>(g_feat_h + (size_t)s1 * FDIM + lane * 4);
                uint2 u2 = *reinterpret_cast<const uint2*>(g_feat_h + (size_t)s2 * FDIM + lane * 4);
                uint2 u3 = *reinterpret_cast<const uint2*>(g_feat_h + (size_t)s3 * FDIM + lane * 4);
                float2 f00 = __half22float2(*reinterpret_cast<__half2*>(&u0.x));
                float2 f01 = __half22float2(*reinterpret_cast<__half2*>(&u0.y));
                float2 f10 = __half22float2(*reinterpret_cast<__half2*>(&u1.x));
                float2 f11 = __half22float2(*reinterpret_cast<__half2*>(&u1.y));
                float2 f20 = __half22float2(*reinterpret_cast<__half2*>(&u2.x));
                float2 f21 = __half22float2(*reinterpret_cast<__half2*>(&u2.y));
                float2 f30 = __half22float2(*reinterpret_cast<__half2*>(&u3.x));
                float2 f31 = __half22float2(*reinterpret_cast<__half2*>(&u3.y));
                a0 += w0.x * f00.x + w1.x * f10.x + w2.x * f20.x + w3.x * f30.x;
                a1 += w0.y * f00.y + w1.y * f10.y + w2.y * f20.y + w3.y * f30.y;
                a2 += w0.z * f01.x + w1.z * f11.x + w2.z * f21.x + w3.z * f31.x;
                a3 += w0.w * f01.y + w1.w * f11.y + w2.w * f21.y + w3.w * f31.y;
            }
            for (; j < m; j++) {
                int   s0 = sm->u.agg.s[wid][j];
                float4 w0 = sm->u.agg.w[wid][j];
                uint2 u0 = *reinterpret_cast<const uint2*>(g_feat_h + (size_t)s0 * FDIM + lane * 4);
                float2 f00 = __half22float2(*reinterpret_cast<__half2*>(&u0.x));
                float2 f01 = __half22float2(*reinterpret_cast<__half2*>(&u0.y));
                a0 += w0.x * f00.x;
                a1 += w0.y * f00.y;
                a2 += w0.z * f01.x;
                a3 += w0.w * f01.y;
            }
            __syncwarp();
        }

#pragma unroll
        for (int off = 16; off; off >>= 1) {
            sx += __shfl_xor_sync(0xffffffffu, sx, off);
            sy += __shfl_xor_sync(0xffffffffu, sy, off);
            sz += __shfl_xor_sync(0xffffffffu, sz, off);
            sw += __shfl_xor_sync(0xffffffffu, sw, off);
        }
        float invx = 1.f / fmaxf(sx, 1e-9f);
        float invy = 1.f / fmaxf(sy, 1e-9f);
        float invz = 1.f / fmaxf(sz, 1e-9f);
        float invw = 1.f / fmaxf(sw, 1e-9f);

        float r0 = a0 * invx + resid[node * FDIM + 0  + lane] + bias[0  + lane];
        float r1 = a1 * invy + resid[node * FDIM + 32 + lane] + bias[32 + lane];
        float r2 = a2 * invz + resid[node * FDIM + 64 + lane] + bias[64 + lane];
        float r3 = a3 * invw + resid[node * FDIM + 96 + lane] + bias[96 + lane];

        if (MODE == 1) {
            out[node * FDIM + 0  + lane] = elu1(r0);
            out[node * FDIM + 32 + lane] = elu1(r1);
            out[node * FDIM + 64 + lane] = elu1(r2);
            out[node * FDIM + 96 + lane] = elu1(r3);
        } else {
            out[node * 32 + lane] = 0.25f * (r0 + r1 + r2 + r3);
        }
    }
}

// -------------------- mega kernel -------------------------------------------
__global__ void __launch_bounds__(TPB, 4) k_mega(
    const float* __restrict__ x,
    const float* __restrict__ W1, const float* __restrict__ al1,
    const float* __restrict__ ar1, const float* __restrict__ b1,
    const float* __restrict__ W2, const float* __restrict__ al2,
    const float* __restrict__ ar2, const float* __restrict__ b2,
    const int* __restrict__ src, const int* __restrict__ dst,
    float* __restrict__ out)
{
    __shared__ SMem sm;
    int bid = blockIdx.x, tid = threadIdx.x;
    if (tid == 0) sm.bsense = 0;

    // ---- P0: zero counts ----
    for (int i = bid * TPB + tid; i < NN; i += GRID * TPB) g_cnt[i] = 0;
    gbar(&sm);                                                        // B1

    // ---- P1: degree count ----
    for (int e = bid * TPB + tid; e < EE; e += GRID * TPB)
        atomicAdd(&g_cnt[dst[e]], 1);
    gbar(&sm);                                                        // B2

    // ---- P2: local scan per 256-segment ----
    if (bid < NSEG) {
        int i = bid * TPB + tid;
        int v = (i < NN) ? g_cnt[i] : 0;
        int lane = tid & 31, w = tid >> 5;
        int xv = v;
#pragma unroll
        for (int off = 1; off < 32; off <<= 1) {
            int y = __shfl_up_sync(0xffffffffu, xv, off);
            if (lane >= off) xv += y;
        }
        if (lane == 31) sm.u.scan.warp[w] = xv;
        __syncthreads();
        if (tid < 8) {
            int y = sm.u.scan.warp[tid];
            int z = y;
#pragma unroll
            for (int off = 1; off < 8; off <<= 1) {
                int q = __shfl_up_sync(0xffu, z, off);
                if ((int)tid >= off) z += q;
            }
            sm.u.scan.woff[tid] = z - y;   // exclusive warp offset
        }
        __syncthreads();
        xv += sm.u.scan.woff[w];
        if (i < NN) g_row[i] = xv - v;     // block-local exclusive
        if (tid == TPB - 1) g_bsum[bid] = xv;
    }
    gbar(&sm);                                                        // B3

    // ---- P3: add segment offsets ----
    if (bid < NSEG) {
        int v = (tid < NSEG) ? g_bsum[tid] : 0;
        int lane = tid & 31, w = tid >> 5;
        int xv = v;
#pragma unroll
        for (int off = 1; off < 32; off <<= 1) {
            int y = __shfl_up_sync(0xffffffffu, xv, off);
            if (lane >= off) xv += y;
        }
        if (lane == 31) sm.u.scan.warp[w] = xv;
        __syncthreads();
        if (tid < 8) {
            int y = sm.u.scan.warp[tid];
            int z = y;
#pragma unroll
            for (int off = 1; off < 8; off <<= 1) {
                int q = __shfl_up_sync(0xffu, z, off);
                if ((int)tid >= off) z += q;
            }
            sm.u.scan.woff[tid] = z - y;
        }
        __syncthreads();
        xv += sm.u.scan.woff[w];
        sm.u.scan.arr[tid] = xv - v;       // exclusive prefix of bsum
        __syncthreads();
        int off = sm.u.scan.arr[bid];
        int i = bid * TPB + tid;
        if (i < NN) {
            int r = g_row[i] + off;
            g_row[i] = r;
            g_pos[i] = r;
        }
    }
    gbar(&sm);                                                        // B4

    // ---- P4: scatter edges to CSR ----
    for (int e = bid * TPB + tid; e < EE; e += GRID * TPB) {
        int d = dst[e];
        int p = atomicAdd(&g_pos[d], 1);
        g_csr_src[p] = src[e];
    }
    gbar(&sm);                                                        // B5

    // ---- P5: layer-1 GEMM + el/er + fp16 emit ----
    gemm_phase(&sm, x, W1, al1, ar1);
    gbar(&sm);                                                        // B6

    // ---- P6: layer-1 agg -> g_h1 ----
    agg_phase<1>(&sm, x, b1, g_h1);
    gbar(&sm);                                                        // B7

    // ---- P7: layer-2 GEMM ----
    gemm_phase(&sm, g_h1, W2, al2, ar2);
    gbar(&sm);                                                        // B8 (even count: sense back to 0)

    // ---- P8: layer-2 agg -> out ----
    agg_phase<2>(&sm, g_h1, b2, out);
}

// -------------------- launch ------------------------------------------------
extern "C" void kernel_launch(void* const* d_in, const int* in_sizes, int n_in,
                              void* d_out, int out_size) {
    const float* x   = (const float*)d_in[0];
    const float* W1  = (const float*)d_in[1];
    const float* al1 = (const float*)d_in[2];
    const float* ar1 = (const float*)d_in[3];
    const float* b1  = (const float*)d_in[4];
    const float* W2  = (const float*)d_in[5];
    const float* al2 = (const float*)d_in[6];
    const float* ar2 = (const float*)d_in[7];
    const float* b2  = (const float*)d_in[8];
    const int*   src = (const int*)d_in[9];
    const int*   dst = (const int*)d_in[10];
    float* out = (float*)d_out;

    k_mega<<<GRID, TPB>>>(x, W1, al1, ar1, b1, W2, al2, ar2, b2, src, dst, out);
}